// round 16
// baseline (speedup 1.0000x reference)
#include <cuda_runtime.h>
#include <cuda_bf16.h>
#include <math.h>
#include <stdint.h>

// ---------------- problem constants ----------------
namespace {
constexpr int kS = 2048;
constexpr int kR = 4096;               // 2 * 2048 tokens
constexpr float kEps = 1e-8f;
constexpr float kScale = 0.08838834764831845f;   // 1/sqrt(128)
constexpr float kLog2e = 1.4426950408889634f;
constexpr float kLogTheta = 9.210340371976184f;  // ln(10000)
}

// ---------------- scratch ----------------
__device__ __nv_bfloat16 g_xh [kR * 1024], g_xl [kR * 1024];
__device__ __nv_bfloat16 g_wph[1024 * 320], g_wpl[1024 * 320];
__device__ float         g_bpack[320];
__device__ float         g_zero[1536];                 // stays 0 (never written)
__device__ float         g_xc [kR * 320];
__device__ __nv_bfloat16 g_xch[kR * 320], g_xcl[kR * 320];
__device__ __nv_bfloat16 g_uqh[128 * 1024], g_uql[128 * 1024];
__device__ __nv_bfloat16 g_ukh[128 * 2560], g_ukl[128 * 2560];
__device__ __nv_bfloat16 g_woh[2048 * 1024], g_wol[2048 * 1024];
__device__ __nv_bfloat16 g_wch[1024 * 1024], g_wcl[1024 * 1024];
__device__ float         g_bcomb[1024];
__device__ float         g_bpart[128 * 1024];
__device__ __nv_bfloat16 g_ukTh[8 * 64 * 128], g_ukTl[8 * 64 * 128];  // Wuk^T per head
__device__ float         g_wqcomb[8 * 128 * 128];  // Wuq_slice @ Wuk_h^T
__device__ float         g_wq  [128 * 1536];       // combined q weight (fp32)
__device__ __nv_bfloat16 g_wqh [128 * 1536], g_wql[128 * 1536];
__device__ float         g_bq  [1536];             // combined q bias
__device__ float         g_qc  [kR * 1536];        // attention-ready Q: [row][h*192+d]
__device__ float         g_ckvr[kR * 192];         // normed ckv 128 | roped kr 64
__device__ __nv_bfloat16 g_ah [kR * 1024], g_al[kR * 1024];  // out_latent split

// ---------------- numeric helpers ----------------
__device__ __forceinline__ uint32_t f2tf(float f) {
    uint32_t r; asm("cvt.rna.tf32.f32 %0, %1;" : "=r"(r) : "f"(f)); return r;
}
__device__ __forceinline__ float ex2(float x) {
    float r; asm("ex2.approx.ftz.f32 %0, %1;" : "=f"(r) : "f"(x)); return r;
}
__device__ __forceinline__ void bsplit(float v, uint16_t& hi, uint16_t& lo) {
    __nv_bfloat16 h = __float2bfloat16(v);
    hi = *(uint16_t*)&h;
    __nv_bfloat16 l = __float2bfloat16(v - __bfloat162float(h));
    lo = *(uint16_t*)&l;
}
__device__ __forceinline__ uint32_t s2u(const void* p) {
    return (uint32_t)__cvta_generic_to_shared(p);
}
__device__ __forceinline__ void ldsm4(uint32_t& r0, uint32_t& r1, uint32_t& r2, uint32_t& r3,
                                      uint32_t addr) {
    asm volatile("ldmatrix.sync.aligned.m8n8.x4.shared.b16 {%0,%1,%2,%3},[%4];"
                 : "=r"(r0), "=r"(r1), "=r"(r2), "=r"(r3) : "r"(addr));
}
__device__ __forceinline__ void ldsm4t(uint32_t& r0, uint32_t& r1, uint32_t& r2, uint32_t& r3,
                                       uint32_t addr) {
    asm volatile("ldmatrix.sync.aligned.m8n8.x4.trans.shared.b16 {%0,%1,%2,%3},[%4];"
                 : "=r"(r0), "=r"(r1), "=r"(r2), "=r"(r3) : "r"(addr));
}
__device__ __forceinline__ void mma8(float& c0, float& c1, float& c2, float& c3,
                                     uint32_t a0, uint32_t a1, uint32_t a2, uint32_t a3,
                                     uint32_t b0, uint32_t b1) {
    asm volatile("mma.sync.aligned.m16n8k8.row.col.f32.tf32.tf32.f32 "
                 "{%0,%1,%2,%3},{%4,%5,%6,%7},{%8,%9},{%0,%1,%2,%3};"
                 : "+f"(c0), "+f"(c1), "+f"(c2), "+f"(c3)
                 : "r"(a0), "r"(a1), "r"(a2), "r"(a3), "r"(b0), "r"(b1));
}
__device__ __forceinline__ void mma16(float& c0, float& c1, float& c2, float& c3,
                                      uint32_t a0, uint32_t a1, uint32_t a2, uint32_t a3,
                                      uint32_t b0, uint32_t b1) {
    asm volatile("mma.sync.aligned.m16n8k16.row.col.f32.bf16.bf16.f32 "
                 "{%0,%1,%2,%3},{%4,%5,%6,%7},{%8,%9},{%0,%1,%2,%3};"
                 : "+f"(c0), "+f"(c1), "+f"(c2), "+f"(c3)
                 : "r"(a0), "r"(a1), "r"(a2), "r"(a3), "r"(b0), "r"(b1));
}
__device__ __forceinline__ void cpa16(uint32_t dst, const void* src, bool pred) {
    int sz = pred ? 16 : 0;
    asm volatile("cp.async.cg.shared.global [%0], [%1], 16, %2;"
                 :: "r"(dst), "l"(src), "r"(sz));
}
__device__ __forceinline__ void cpacommit() {
    asm volatile("cp.async.commit_group;");
}
template <int N> __device__ __forceinline__ void cpawait() {
    asm volatile("cp.async.wait_group %0;" :: "n"(N));
}

// ---------------- merged split prep: all 4 fp32->bf16 hi/lo splits -----------
// segments (in 4-float groups): x 1048576 | uq 32768 | uk 81920 | wo 524288
__global__ void split_all_kernel(
    const float* __restrict__ sx,  __nv_bfloat16* __restrict__ xh,  __nv_bfloat16* __restrict__ xl,
    const float* __restrict__ suq, __nv_bfloat16* __restrict__ uqh, __nv_bfloat16* __restrict__ uql,
    const float* __restrict__ suk, __nv_bfloat16* __restrict__ ukh, __nv_bfloat16* __restrict__ ukl,
    const float* __restrict__ swo, __nv_bfloat16* __restrict__ woh, __nv_bfloat16* __restrict__ wol)
{
    int g = blockIdx.x * 256 + threadIdx.x;     // group index (4 floats)
    const float* src; __nv_bfloat16 *hi, *lo;
    if (g < 1048576)      { src = sx;  hi = xh;  lo = xl; }
    else if (g < 1081344) { g -= 1048576; src = suq; hi = uqh; lo = uql; }
    else if (g < 1163264) { g -= 1081344; src = suk; hi = ukh; lo = ukl; }
    else                  { g -= 1163264; src = swo; hi = woh; lo = wol; }
    int i = g * 4;
    float4 v = *(const float4*)(src + i);
    uint16_t h[4], l[4];
    bsplit(v.x, h[0], l[0]); bsplit(v.y, h[1], l[1]);
    bsplit(v.z, h[2], l[2]); bsplit(v.w, h[3], l[3]);
    *(uint2*)(hi + i) = *(uint2*)h;
    *(uint2*)(lo + i) = *(uint2*)l;
}

__global__ void pack_split_w_kernel(const float* __restrict__ wdq, const float* __restrict__ bdq,
                                    const float* __restrict__ wdkv, const float* __restrict__ bdkv,
                                    __nv_bfloat16* __restrict__ wh, __nv_bfloat16* __restrict__ wl,
                                    float* __restrict__ bp)
{
    int idx = blockIdx.x * 256 + threadIdx.x;
    if (idx < 1024 * 320) {
        int k = idx / 320, c = idx - k * 320;
        float v = (c < 128) ? wdq[k * 128 + c] : wdkv[k * 192 + (c - 128)];
        uint16_t h, l; bsplit(v, h, l);
        wh[idx] = *(__nv_bfloat16*)&h;
        wl[idx] = *(__nv_bfloat16*)&l;
    }
    if (idx < 320) bp[idx] = (idx < 128) ? bdq[idx] : bdkv[idx - 128];
}

// ---------------- Wuk^T per head, split to bf16 hi/lo ----------------
// ukT[(h*64+d)*128 + l] = wukuv[l*2560 + h*64 + d]
__global__ void ukT_split_kernel(const float* __restrict__ wukuv,
                                 __nv_bfloat16* __restrict__ th, __nv_bfloat16* __restrict__ tl)
{
    int idx = blockIdx.x * 256 + threadIdx.x;   // 65536
    int h = idx >> 13, rem = idx & 8191, d = rem >> 7, l = rem & 127;
    float v = wukuv[(size_t)l * 2560 + h * 64 + d];
    uint16_t hh, ll; bsplit(v, hh, ll);
    th[idx] = *(__nv_bfloat16*)&hh;
    tl[idx] = *(__nv_bfloat16*)&ll;
}

// ---------------- assemble combined q weight W_q' (fp32) + bias ----------------
// wq[c][h*192+j]: j<128 -> wqcomb[h][c][j]; j<160 -> Wuq[c][h*96+64+j-128];
//                 j>=160 -> Wuq[c][768+h*32+j-160]
__global__ void wq_pack_kernel(const float* __restrict__ wqcomb,
                               const float* __restrict__ wuq, float* __restrict__ wq)
{
    int idx = blockIdx.x * 256 + threadIdx.x;   // 128*1536
    int c = idx / 1536, col = idx - c * 1536;
    int h = col / 192, j = col - h * 192;
    float v;
    if (j < 128)      v = wqcomb[(h * 128 + c) * 128 + j];
    else if (j < 160) v = wuq[(size_t)c * 1024 + h * 96 + 64 + (j - 128)];
    else              v = wuq[(size_t)c * 1024 + 768 + h * 32 + (j - 160)];
    wq[idx] = v;
}
__global__ void bq_pack_kernel(const float* __restrict__ wukuv,
                               const float* __restrict__ buq, float* __restrict__ bq)
{
    int col = blockIdx.x * 256 + threadIdx.x;   // 1536
    int h = col / 192, j = col - h * 192;
    float v;
    if (j < 128) {
        float acc = 0.0f;
        for (int d = 0; d < 64; d++)
            acc += wukuv[(size_t)j * 2560 + h * 64 + d] * buq[h * 96 + d];
        v = acc;
    } else if (j < 160) v = buq[h * 96 + 64 + (j - 128)];
    else                v = buq[768 + h * 32 + (j - 160)];
    bq[col] = v;
}

// ---------------- fp32 -> bf16 hi/lo split (generic, small) ----------------
__global__ void split4_kernel(const float* __restrict__ src,
                              __nv_bfloat16* __restrict__ hi,
                              __nv_bfloat16* __restrict__ lo, int n)
{
    int i = (blockIdx.x * 256 + threadIdx.x) * 4;
    if (i < n) {
        float4 v = *(const float4*)(src + i);
        uint16_t h[4], l[4];
        bsplit(v.x, h[0], l[0]); bsplit(v.y, h[1], l[1]);
        bsplit(v.z, h[2], l[2]); bsplit(v.w, h[3], l[3]);
        *(uint2*)(hi + i) = *(uint2*)h;
        *(uint2*)(lo + i) = *(uint2*)l;
    }
}

// b_comb[j] = w_o_b[j] + sum_i w_ukuv_b[512+i] * w_o[i][j] : 2-stage reduction
__global__ void bcomb_part_kernel(const float* __restrict__ wo,
                                  const float* __restrict__ bkv, float* __restrict__ part)
{
    int j = blockIdx.x * 128 + threadIdx.x;   // grid.x = 8
    int ib = blockIdx.y;                      // 128 splits of 16 rows
    float acc = 0.0f;
    int i0 = ib * 16;
#pragma unroll 4
    for (int i = i0; i < i0 + 16; i++) acc += bkv[512 + i] * wo[(size_t)i * 1024 + j];
    part[ib * 1024 + j] = acc;
}
__global__ void bcomb_reduce_kernel(const float* __restrict__ part,
                                    const float* __restrict__ wob, float* __restrict__ bc)
{
    int j = blockIdx.x * 128 + threadIdx.x;
    float acc = wob[j];
#pragma unroll
    for (int ib = 0; ib < 128; ib++) acc += part[ib * 1024 + j];
    bc[j] = acc;
}

// ================= GEMM: C = A @ B + bias, bf16x3, cp.async 3-stage, z-batched ====
// Optional: bf16 split output (Ch/Cl), or fused q-RoPE on cols%192>=160 (rope_pos).
constexpr int GAs = 40;
constexpr int GBs = 136;
constexpr int kStgA  = 64 * GAs * 2;
constexpr int kStgB  = 32 * GBs * 2;
constexpr int kStage = 2 * kStgA + 2 * kStgB;   // 27648
constexpr int kGemmSmem = 3 * kStage;           // 82944 B

__global__ __launch_bounds__(256) void gemm_cp_kernel(
    int N, int K, int lda, size_t aZ, size_t bZ, size_t cZ,
    const __nv_bfloat16* __restrict__ Agh, const __nv_bfloat16* __restrict__ Agl,
    const __nv_bfloat16* __restrict__ Bgh, const __nv_bfloat16* __restrict__ Bgl,
    const float* __restrict__ bias, float* __restrict__ C,
    __nv_bfloat16* __restrict__ Ch, __nv_bfloat16* __restrict__ Cl,
    const int* __restrict__ rope_pos)
{
    extern __shared__ char smg[];
    const int tid = threadIdx.x, w = tid >> 5, lane = tid & 31;
    const int gid = lane >> 2, tig = lane & 3;
    const int m0 = (w >> 2) * 32, n0 = (w & 3) * 32;
    const int bR = blockIdx.y, bC = blockIdx.x, z = blockIdx.z;
    const uint32_t smbase = s2u(smg);
    const __nv_bfloat16* Ah_g = Agh + (size_t)z * aZ;
    const __nv_bfloat16* Al_g = Agl + (size_t)z * aZ;
    const __nv_bfloat16* Bh_g = Bgh + (size_t)z * bZ;
    const __nv_bfloat16* Bl_g = Bgl + (size_t)z * bZ;

    float acc[2][4][4];
#pragma unroll
    for (int mt = 0; mt < 2; mt++)
#pragma unroll
        for (int nt = 0; nt < 4; nt++)
#pragma unroll
            for (int e = 0; e < 4; e++) acc[mt][nt][e] = 0.0f;

    const int ar = tid >> 2, ak = (tid & 3) * 8;

    auto load_stage = [&](int st, int k0) {
        uint32_t b = smbase + st * kStage;
        size_t aoff = (size_t)(bR * 64 + ar) * lda + k0 + ak;
        cpa16(b + (ar * GAs + ak) * 2,         Ah_g + aoff, true);
        cpa16(b + kStgA + (ar * GAs + ak) * 2, Al_g + aoff, true);
#pragma unroll
        for (int q2 = 0; q2 < 2; q2++) {
            int c = tid + q2 * 256;
            int brw = c >> 4, bcl = (c & 15) * 8;
            int gc = bC * 128 + bcl;
            bool p = gc < N;
            size_t boff = (size_t)(k0 + brw) * N + (p ? gc : 0);
            cpa16(b + 2 * kStgA + (brw * GBs + bcl) * 2,         Bh_g + boff, p);
            cpa16(b + 2 * kStgA + kStgB + (brw * GBs + bcl) * 2, Bl_g + boff, p);
        }
    };

    const int nkb = K >> 5;
    load_stage(0, 0);
    cpacommit();

    for (int kb = 0; kb < nkb; kb++) {
        if (kb + 1 < nkb) load_stage((kb + 1) % 3, (kb + 1) * 32);
        cpacommit();
        cpawait<1>();
        __syncthreads();

        uint32_t b = smbase + (kb % 3) * kStage;
        uint32_t aHi = b + ((lane & 15) * GAs + (lane >> 4) * 8) * 2;
        uint32_t aLo = aHi + kStgA;
        uint32_t bHi = b + 2 * kStgA + ((lane & 15) * GBs + (lane >> 4) * 8) * 2;
        uint32_t bLo = bHi + kStgB;

#pragma unroll
        for (int ks = 0; ks < 2; ks++) {
            const int k16 = ks * 16;
            uint32_t ah[2][4], al[2][4], bh[2][4], bl[2][4];
#pragma unroll
            for (int mt = 0; mt < 2; mt++) {
                uint32_t off = ((m0 + mt * 16) * GAs + k16) * 2;
                ldsm4(ah[mt][0], ah[mt][1], ah[mt][2], ah[mt][3], aHi + off);
                ldsm4(al[mt][0], al[mt][1], al[mt][2], al[mt][3], aLo + off);
            }
#pragma unroll
            for (int np = 0; np < 2; np++) {
                uint32_t off = (k16 * GBs + n0 + np * 16) * 2;
                ldsm4t(bh[np][0], bh[np][1], bh[np][2], bh[np][3], bHi + off);
                ldsm4t(bl[np][0], bl[np][1], bl[np][2], bl[np][3], bLo + off);
            }
#pragma unroll
            for (int mt = 0; mt < 2; mt++)
#pragma unroll
                for (int nt = 0; nt < 4; nt++) {
                    float* c = acc[mt][nt];
                    uint32_t b0h = bh[nt >> 1][(nt & 1) * 2], b1h = bh[nt >> 1][(nt & 1) * 2 + 1];
                    uint32_t b0l = bl[nt >> 1][(nt & 1) * 2], b1l = bl[nt >> 1][(nt & 1) * 2 + 1];
                    mma16(c[0], c[1], c[2], c[3],
                          ah[mt][0], ah[mt][1], ah[mt][2], ah[mt][3], b0h, b1h);
                    mma16(c[0], c[1], c[2], c[3],
                          ah[mt][0], ah[mt][1], ah[mt][2], ah[mt][3], b0l, b1l);
                    mma16(c[0], c[1], c[2], c[3],
                          al[mt][0], al[mt][1], al[mt][2], al[mt][3], b0h, b1h);
                }
        }
        // no trailing barrier: 3-stage buffering guarantees reuse distance >= 2 syncs
    }

#pragma unroll
    for (int mt = 0; mt < 2; mt++)
#pragma unroll
        for (int nt = 0; nt < 4; nt++) {
            int row = bR * 64 + m0 + mt * 16 + gid;
            int col = bC * 128 + n0 + nt * 8 + tig * 2;
            if (col < N) {
                float b0 = bias[col], b1 = bias[col + 1];
                float r00 = acc[mt][nt][0] + b0, r01 = acc[mt][nt][1] + b1;
                float r10 = acc[mt][nt][2] + b0, r11 = acc[mt][nt][3] + b1;
                if (rope_pos && (col % 192) >= 160) {
                    // q-RoPE: this thread owns one (even, odd) rope pair; 2i = col&31
                    float invf = expf(-((float)(col & 31) * (1.0f / 32.0f)) * kLogTheta);
                    float s0, c0; sincosf((float)rope_pos[row] * invf, &s0, &c0);
                    float s1, c1; sincosf((float)rope_pos[row + 8] * invf, &s1, &c1);
                    float e0 = r00, o0 = r01, e1 = r10, o1 = r11;
                    r00 = e0 * c0 - o0 * s0;  r01 = e0 * s0 + o0 * c0;
                    r10 = e1 * c1 - o1 * s1;  r11 = e1 * s1 + o1 * c1;
                }
                if (Ch) {
                    __nv_bfloat16* Chz = Ch + (size_t)z * cZ;
                    __nv_bfloat16* Clz = Cl + (size_t)z * cZ;
                    uint16_t h0, l0, h1, l1;
                    bsplit(r00, h0, l0); bsplit(r01, h1, l1);
                    *(uint32_t*)(Chz + (size_t)row * N + col) = (uint32_t)h0 | ((uint32_t)h1 << 16);
                    *(uint32_t*)(Clz + (size_t)row * N + col) = (uint32_t)l0 | ((uint32_t)l1 << 16);
                    bsplit(r10, h0, l0); bsplit(r11, h1, l1);
                    *(uint32_t*)(Chz + (size_t)(row + 8) * N + col) = (uint32_t)h0 | ((uint32_t)h1 << 16);
                    *(uint32_t*)(Clz + (size_t)(row + 8) * N + col) = (uint32_t)l0 | ((uint32_t)l1 << 16);
                } else {
                    float* Cz = C + (size_t)z * cZ;
                    *(float2*)(Cz + (size_t)row * N + col) = make_float2(r00, r01);
                    *(float2*)(Cz + (size_t)(row + 8) * N + col) = make_float2(r10, r11);
                }
            }
        }
}

// ---------------- fused cq-norm + ckv-norm + k-rope -> xch/xcl + ckvr ----------
__global__ void normpack_kernel(const float* __restrict__ xc,
                                const float* __restrict__ qw, const float* __restrict__ kvw,
                                const int* __restrict__ pos_ids,
                                __nv_bfloat16* __restrict__ xch, __nv_bfloat16* __restrict__ xcl,
                                float* __restrict__ ckvr)
{
    const int row = blockIdx.x;
    const int tid = threadIdx.x;          // 256
    const int half = tid >> 7, t = tid & 127;
    __shared__ float red[8];
    float v = xc[(size_t)row * 320 + half * 128 + t];
    float ss = v * v;
#pragma unroll
    for (int o = 16; o > 0; o >>= 1) ss += __shfl_xor_sync(0xffffffffu, ss, o);
    if ((tid & 31) == 0) red[tid >> 5] = ss;
    __syncthreads();
    float sum = half ? (red[4] + red[5] + red[6] + red[7])
                     : (red[0] + red[1] + red[2] + red[3]);
    float inv = rsqrtf(sum * (1.0f / 128.0f) + kEps);
    const float* wsel = half ? kvw : qw;
    float r = wsel[t] * v * inv;
    uint16_t h, l; bsplit(r, h, l);
    xch[(size_t)row * 320 + half * 128 + t] = *(__nv_bfloat16*)&h;
    xcl[(size_t)row * 320 + half * 128 + t] = *(__nv_bfloat16*)&l;
    if (half == 1) ckvr[(size_t)row * 192 + t] = r;   // V/latent-K part

    if (half == 1 && t < 32) {
        const int i = t;
        float pos = (float)pos_ids[row];
        float invf = expf(-((float)(2 * i) / 64.0f) * kLogTheta);
        float sv, cv;
        sincosf(pos * invf, &sv, &cv);
        const float* rb = xc + (size_t)row * 320 + 256;
        float xe = rb[2 * i], xo = rb[2 * i + 1];
        ckvr[(size_t)row * 192 + 128 + 2 * i]     = xe * cv - xo * sv;
        ckvr[(size_t)row * 192 + 128 + 2 * i + 1] = xe * sv + xo * cv;
    }
}

// ================= latent flash attention (tf32, absorbed K/V) ==================
// Grid (16, 8, 2). 8 warps, BQ=128, BKT=64. 3-stage cp.async, no-max exp2 softmax.
// K rows carry a per-row 16B-chunk rotation s(j)=2*((j&1)+((j>>1)&1)) so that
// QK B-frags load as single conflict-free LDS.128 and PV LDS.64 stays conflict-free.
constexpr int KSr = 200;   // u32 stride per latent row
constexpr int PSr = 68;    // 64 cols + 4 pad
constexpr int kAStage = 64 * KSr * 4;                      // 51200
constexpr int kAttnSmem = 3 * kAStage + 8 * 16 * PSr * 4;  // 188416

__device__ __forceinline__ int rowrot(int j) {   // chunk rotation per row (period 4)
    return 2 * ((j & 1) + ((j >> 1) & 1));
}

__global__ __launch_bounds__(256, 1) void attn_tc_kernel(
    const float* __restrict__ qc, const float* __restrict__ ckvr,
    __nv_bfloat16* __restrict__ oh, __nv_bfloat16* __restrict__ ol)
{
    extern __shared__ char smx[];
    const int qt = blockIdx.x, h = blockIdx.y, b = blockIdx.z;
    const int tid = threadIdx.x, w = tid >> 5, lane = tid & 31;
    const int gid = lane >> 2, tig = lane & 3;
    const size_t rowbase = (size_t)b * kS;
    const int q0 = qt * 128, m0 = w * 16;
    const uint32_t smbase = s2u(smx);

    auto load_kv = [&](int st, int kt) {
        uint32_t bb = smbase + st * kAStage;
        int j = tid >> 2, q4 = tid & 3;             // row j (0..63), 12-chunk quarter
        const int sj = rowrot(j);
        const float* src = ckvr + (rowbase + kt * 64 + j) * 192 + q4 * 48;
#pragma unroll
        for (int i = 0; i < 12; i++) {
            int c = q4 * 12 + i;
            int p = c + sj; if (p >= 48) p -= 48;
            cpa16(bb + (j * KSr + p * 4) * 4, src + i * 4, true);
        }
    };

    // per-thread QK column table: chunk pos for kp, given this thread's gid rotation
    const int soff = rowrot(gid);
    int colk[12];
#pragma unroll
    for (int kp = 0; kp < 12; kp++) {
        int p = 4 * kp + tig + soff; if (p >= 48) p -= 48;
        colk[kp] = p * 4;
    }
    const int spv = rowrot(tig) * 4;   // PV column offset (u32)

    // ---- preload 192-dim Q fragments: qf[kp][e], logical k = 16kp + 4tig + 2e ----
    const float qsc = kScale * kLog2e;
    uint32_t qf[12][2][4];
    {
        size_t r0 = rowbase + q0 + m0 + gid;
        const float* q0p = qc + r0 * 1536 + h * 192;
        const float* q1p = qc + (r0 + 8) * 1536 + h * 192;
#pragma unroll
        for (int kp = 0; kp < 12; kp++) {
#pragma unroll
            for (int e = 0; e < 2; e++) {
                int d0 = kp * 16 + tig * 4 + e * 2;
                qf[kp][e][0] = f2tf(q0p[d0] * qsc);
                qf[kp][e][1] = f2tf(q1p[d0] * qsc);
                qf[kp][e][2] = f2tf(q0p[d0 + 1] * qsc);
                qf[kp][e][3] = f2tf(q1p[d0 + 1] * qsc);
            }
        }
    }

    float oacc[16][4];
#pragma unroll
    for (int nt = 0; nt < 16; nt++)
#pragma unroll
        for (int e = 0; e < 4; e++) oacc[nt][e] = 0.0f;
    float lacc0 = 0.0f, lacc1 = 0.0f;

    load_kv(0, 0);
    cpacommit();

    constexpr int nkt = kS / 64;
    for (int kt = 0; kt < nkt; kt++) {
        if (kt + 1 < nkt) load_kv((kt + 1) % 3, kt + 1);
        cpacommit();
        cpawait<1>();
        __syncthreads();

        uint32_t* Ks = (uint32_t*)(smx + (kt % 3) * kAStage);
        uint32_t* Ps = (uint32_t*)(smx + 3 * kAStage);

        // ---- S = Q @ K^T : one LDS.128 feeds two mma8 ----
        float sacc[8][4];
#pragma unroll
        for (int nt = 0; nt < 8; nt++)
#pragma unroll
            for (int e = 0; e < 4; e++) sacc[nt][e] = 0.0f;
#pragma unroll
        for (int kp = 0; kp < 12; kp++) {
#pragma unroll
            for (int nt = 0; nt < 8; nt++) {
                uint4 vv = *(uint4*)&Ks[(nt * 8 + gid) * KSr + colk[kp]];
                mma8(sacc[nt][0], sacc[nt][1], sacc[nt][2], sacc[nt][3],
                     qf[kp][0][0], qf[kp][0][1], qf[kp][0][2], qf[kp][0][3], vv.x, vv.y);
                mma8(sacc[nt][0], sacc[nt][1], sacc[nt][2], sacc[nt][3],
                     qf[kp][1][0], qf[kp][1][1], qf[kp][1][2], qf[kp][1][3], vv.z, vv.w);
            }
        }

        // ---- no-max softmax: p = 2^s ; store tf32 via RNA cvt (unbiased) ----
        uint32_t* pw = Ps + w * 16 * PSr;
#pragma unroll
        for (int nt = 0; nt < 8; nt++) {
            float p0 = ex2(sacc[nt][0]);
            float p1 = ex2(sacc[nt][1]);
            float p2 = ex2(sacc[nt][2]);
            float p3 = ex2(sacc[nt][3]);
            lacc0 += p0 + p1;
            lacc1 += p2 + p3;
            int c = nt * 8 + tig * 2;
            pw[gid * PSr + c]           = f2tf(p0);
            pw[gid * PSr + c + 1]       = f2tf(p1);
            pw[(gid + 8) * PSr + c]     = f2tf(p2);
            pw[(gid + 8) * PSr + c + 1] = f2tf(p3);
        }
        __syncwarp();

        // ---- O += P @ V : V = latent chunks of Ks (rotated cols) ----
#pragma unroll
        for (int ks = 0; ks < 8; ks++) {
            uint32_t a0 = pw[gid * PSr + ks * 8 + tig];
            uint32_t a1 = pw[(gid + 8) * PSr + ks * 8 + tig];
            uint32_t a2 = pw[gid * PSr + ks * 8 + tig + 4];
            uint32_t a3 = pw[(gid + 8) * PSr + ks * 8 + tig + 4];
#pragma unroll
            for (int nt2 = 0; nt2 < 8; nt2++) {
                int colv = (nt2 * 4 + (gid >> 1)) * 4 + spv + (gid & 1) * 2;
                uint2 v0 = *(uint2*)&Ks[(ks * 8 + tig) * KSr + colv];
                uint2 v1 = *(uint2*)&Ks[(ks * 8 + tig + 4) * KSr + colv];
                float* cE = oacc[nt2 * 2];
                float* cO = oacc[nt2 * 2 + 1];
                mma8(cE[0], cE[1], cE[2], cE[3], a0, a1, a2, a3, v0.x, v1.x);
                mma8(cO[0], cO[1], cO[2], cO[3], a0, a1, a2, a3, v0.y, v1.y);
            }
        }
        // no trailing barrier: 3-stage buffering covers the write-after-read hazard
    }

    // ---- final l reduction ----
    lacc0 += __shfl_xor_sync(0xffffffffu, lacc0, 1);
    lacc0 += __shfl_xor_sync(0xffffffffu, lacc0, 2);
    lacc1 += __shfl_xor_sync(0xffffffffu, lacc1, 1);
    lacc1 += __shfl_xor_sync(0xffffffffu, lacc1, 2);
    const float il0 = 1.0f / lacc0, il1 = 1.0f / lacc1;

    // ---- epilogue: un-interleave, normalize, split bf16 -> out_latent ----
    size_t row0 = rowbase + q0 + m0 + gid;
#pragma unroll
    for (int nt2 = 0; nt2 < 8; nt2++) {
        const float* cE = oacc[nt2 * 2];
        const float* cO = oacc[nt2 * 2 + 1];
        int col = h * 128 + nt2 * 16 + tig * 4;
        float v0[4] = {cE[0] * il0, cO[0] * il0, cE[1] * il0, cO[1] * il0};
        float v1[4] = {cE[2] * il1, cO[2] * il1, cE[3] * il1, cO[3] * il1};
        uint16_t h0[4], l0[4], h1[4], l1[4];
#pragma unroll
        for (int e = 0; e < 4; e++) { bsplit(v0[e], h0[e], l0[e]); bsplit(v1[e], h1[e], l1[e]); }
        *(uint2*)(oh + row0 * 1024 + col)       = *(uint2*)h0;
        *(uint2*)(ol + row0 * 1024 + col)       = *(uint2*)l0;
        *(uint2*)(oh + (row0 + 8) * 1024 + col) = *(uint2*)h1;
        *(uint2*)(ol + (row0 + 8) * 1024 + col) = *(uint2*)l1;
    }
}

// ---------------- launch ----------------
extern "C" void kernel_launch(void* const* d_in, const int* in_sizes, int n_in,
                              void* d_out, int out_size)
{
    const float* x         = (const float*)d_in[0];
    const int*   pos       = (const int*)  d_in[1];
    const float* w_dq_w    = (const float*)d_in[2];
    const float* w_dq_b    = (const float*)d_in[3];
    const float* q_norm_w  = (const float*)d_in[4];
    const float* w_uq_w    = (const float*)d_in[5];
    const float* w_uq_b    = (const float*)d_in[6];
    const float* w_dkv_w   = (const float*)d_in[7];
    const float* w_dkv_b   = (const float*)d_in[8];
    const float* kv_norm_w = (const float*)d_in[9];
    const float* w_ukuv_w  = (const float*)d_in[10];
    const float* w_ukuv_b  = (const float*)d_in[11];
    const float* w_o_w     = (const float*)d_in[12];
    const float* w_o_b     = (const float*)d_in[13];
    float* out = (float*)d_out;

    __nv_bfloat16 *xh, *xl, *wph, *wpl, *xch, *xcl, *uqh, *uql, *ukh, *ukl,
                  *woh, *wol, *wch, *wcl, *ah, *al, *ukTh, *ukTl, *wqh, *wql;
    float *bp, *zero, *xc, *qcbuf, *ckvr, *bcomb, *bpart, *wqcomb, *wq, *bq;
    cudaGetSymbolAddress((void**)&xh,  g_xh);   cudaGetSymbolAddress((void**)&xl,  g_xl);
    cudaGetSymbolAddress((void**)&wph, g_wph);  cudaGetSymbolAddress((void**)&wpl, g_wpl);
    cudaGetSymbolAddress((void**)&bp,  g_bpack);
    cudaGetSymbolAddress((void**)&zero, g_zero);
    cudaGetSymbolAddress((void**)&xc,  g_xc);
    cudaGetSymbolAddress((void**)&xch, g_xch);  cudaGetSymbolAddress((void**)&xcl, g_xcl);
    cudaGetSymbolAddress((void**)&uqh, g_uqh);  cudaGetSymbolAddress((void**)&uql, g_uql);
    cudaGetSymbolAddress((void**)&ukh, g_ukh);  cudaGetSymbolAddress((void**)&ukl, g_ukl);
    cudaGetSymbolAddress((void**)&woh, g_woh);  cudaGetSymbolAddress((void**)&wol, g_wol);
    cudaGetSymbolAddress((void**)&wch, g_wch);  cudaGetSymbolAddress((void**)&wcl, g_wcl);
    cudaGetSymbolAddress((void**)&bcomb, g_bcomb);
    cudaGetSymbolAddress((void**)&bpart, g_bpart);
    cudaGetSymbolAddress((void**)&ukTh, g_ukTh); cudaGetSymbolAddress((void**)&ukTl, g_ukTl);
    cudaGetSymbolAddress((void**)&wqcomb, g_wqcomb);
    cudaGetSymbolAddress((void**)&wq,  g_wq);
    cudaGetSymbolAddress((void**)&wqh, g_wqh);  cudaGetSymbolAddress((void**)&wql, g_wql);
    cudaGetSymbolAddress((void**)&bq,  g_bq);
    cudaGetSymbolAddress((void**)&qcbuf, g_qc);
    cudaGetSymbolAddress((void**)&ckvr, g_ckvr);
    cudaGetSymbolAddress((void**)&ah,  g_ah);   cudaGetSymbolAddress((void**)&al,  g_al);

    cudaFuncSetAttribute(gemm_cp_kernel,
                         cudaFuncAttributeMaxDynamicSharedMemorySize, kGemmSmem);
    cudaFuncSetAttribute(attn_tc_kernel,
                         cudaFuncAttributeMaxDynamicSharedMemorySize, kAttnSmem);

    // ---- pre-split operands (merged kernel + packed down-proj weights) ----
    split_all_kernel<<<6592, 256>>>(x, xh, xl, w_uq_w, uqh, uql,
                                    w_ukuv_w, ukh, ukl, w_o_w, woh, wol);
    pack_split_w_kernel<<<1280, 256>>>(w_dq_w, w_dq_b, w_dkv_w, w_dkv_b, wph, wpl, bp);
    ukT_split_kernel<<<256, 256>>>(w_ukuv_w, ukTh, ukTl);

    // ---- absorbed output weights: W_comb[h] = Wuv_h @ Wo_h ; b_comb ----
    gemm_cp_kernel<<<dim3(8, 2, 8), 256, kGemmSmem>>>(
        1024, 256, 2560, (size_t)256, (size_t)256 * 1024, (size_t)128 * 1024,
        ukh + 512, ukl + 512, woh, wol, zero, nullptr, wch, wcl, nullptr);
    bcomb_part_kernel<<<dim3(8, 128), 128>>>(w_o_w, w_ukuv_b, bpart);
    bcomb_reduce_kernel<<<8, 128>>>(bpart, w_o_b, bcomb);

    // ---- absorbed q weights: W_qcomb[h] = Wuq_slice_h @ Wuk_h^T ; assemble W_q' ----
    gemm_cp_kernel<<<dim3(1, 2, 8), 256, kGemmSmem>>>(
        128, 64, 1024, (size_t)96, (size_t)64 * 128, (size_t)128 * 128,
        uqh, uql, ukTh, ukTl, zero, wqcomb, nullptr, nullptr, nullptr);
    wq_pack_kernel<<<768, 256>>>(wqcomb, w_uq_w, wq);
    bq_pack_kernel<<<6, 256>>>(w_ukuv_w, w_uq_b, bq);
    split4_kernel<<<192, 256>>>(wq, wqh, wql, 128 * 1536);

    // ---- fused down-projection + norms + k-rope ----
    gemm_cp_kernel<<<dim3(3, 64, 1), 256, kGemmSmem>>>(
        320, 1024, 1024, 0, 0, 0, xh, xl, wph, wpl, bp, xc, nullptr, nullptr, nullptr);
    normpack_kernel<<<kR, 256>>>(xc, q_norm_w, kv_norm_w, pos, xch, xcl, ckvr);

    // ---- combined q projection (q_eff + nope-tail + roped rope, per head) ----
    gemm_cp_kernel<<<dim3(12, 64, 1), 256, kGemmSmem>>>(
        1536, 128, 320, 0, 0, 0, xch, xcl, wqh, wql, bq, qcbuf, nullptr, nullptr, pos);

    // ---- latent attention (BQ=128, BKT=64) ----
    attn_tc_kernel<<<dim3(16, 8, 2), 256, kAttnSmem>>>(qcbuf, ckvr, ah, al);

    // ---- combined output projection ----
    gemm_cp_kernel<<<dim3(8, 64, 1), 256, kGemmSmem>>>(
        1024, 1024, 1024, 0, 0, 0, ah, al, wch, wcl, bcomb, out, nullptr, nullptr, nullptr);
}